// round 6
// baseline (speedup 1.0000x reference)
#include <cuda_runtime.h>
#include <math.h>

// Problem constants
#define NN 16
#define CC 256
#define HH 96
#define WW 96
#define HW (HH*WW)          // 9216
#define RED 16
#define HID (CC/RED)        // 16
#define KK 3
#define DYN (CC*KK*KK)      // 2304
#define EPS 1e-5f

// Scratch (allocation-free rule: __device__ globals)
__device__ float d_g[NN*CC];      // sigmoid gate per (n,c)
__device__ float d_gap[NN*CC];    // g * mean  (== mean of srm)
__device__ float d_filt[NN*DYN];  // g-folded dynamic 3x3 filters

// ---------------------------------------------------------------------------
// Kernel 1: per-(n,c) mean/std -> gate g, gap = g*mean   (71.7% DRAM, keep)
// ---------------------------------------------------------------------------
__global__ void __launch_bounds__(256) stats_kernel(const float* __restrict__ x,
                                                    const float* __restrict__ cfc) {
    int nc = blockIdx.x;
    const float4* xp = (const float4*)(x + (size_t)nc * HW);

    float s = 0.f, s2 = 0.f;
    #pragma unroll
    for (int i = threadIdx.x; i < HW/4; i += 256) {
        float4 v = xp[i];
        s  += v.x + v.y + v.z + v.w;
        s2 += v.x*v.x + v.y*v.y + v.z*v.z + v.w*v.w;
    }
    #pragma unroll
    for (int o = 16; o; o >>= 1) {
        s  += __shfl_xor_sync(0xffffffffu, s,  o);
        s2 += __shfl_xor_sync(0xffffffffu, s2, o);
    }
    __shared__ float ss[8], ss2[8];
    int w = threadIdx.x >> 5;
    if ((threadIdx.x & 31) == 0) { ss[w] = s; ss2[w] = s2; }
    __syncthreads();
    if (threadIdx.x == 0) {
        s = 0.f; s2 = 0.f;
        #pragma unroll
        for (int i = 0; i < 8; i++) { s += ss[i]; s2 += ss2[i]; }
        float mean = s * (1.f / (float)HW);
        float var  = (s2 - s * mean) * (1.f / (float)(HW - 1));  // unbiased
        float stdv = sqrtf(var + EPS);
        int c = nc & (CC - 1);
        float z = mean * cfc[2*c] + stdv * cfc[2*c + 1];
        float g = 1.f / (1.f + __expf(-z));
        d_g[nc]   = g;
        d_gap[nc] = g * mean;
    }
}

// ---------------------------------------------------------------------------
// Kernel 2: tiny MLP -> dynamic filters (g folded in)
// ---------------------------------------------------------------------------
__global__ void __launch_bounds__(256) mlp_kernel(const float* __restrict__ w1,
                                                  const float* __restrict__ b1,
                                                  const float* __restrict__ w2,
                                                  const float* __restrict__ b2) {
    int n = blockIdx.x;
    __shared__ float gap_s[CC];
    __shared__ float hid_s[HID];

    gap_s[threadIdx.x] = d_gap[n*CC + threadIdx.x];
    __syncthreads();

    {
        int r = threadIdx.x >> 4;
        int p = threadIdx.x & 15;
        const float* wr = w1 + r * CC;
        float acc = 0.f;
        #pragma unroll
        for (int c = p; c < CC; c += 16) acc += gap_s[c] * wr[c];
        #pragma unroll
        for (int o = 8; o; o >>= 1) acc += __shfl_xor_sync(0xffffffffu, acc, o);
        if (p == 0) hid_s[r] = fmaxf(acc + b1[r], 0.f);
    }
    __syncthreads();

    for (int o = threadIdx.x; o < DYN; o += 256) {
        const float* wr = w2 + o * HID;
        float acc = b2[o];
        #pragma unroll
        for (int r = 0; r < HID; r++) acc += hid_s[r] * wr[r];
        int c = o / (KK*KK);
        d_filt[n*DYN + o] = acc * d_g[n*CC + c];
    }
}

// ---------------------------------------------------------------------------
// Kernel 3: depthwise 3x3 conv, split into 2 half-tiles per (n,c).
// grid = N*C*2, 192 threads, smem = 50x98 tile (19.6KB) -> 8 blocks/SM.
// Each thread: 4 cols x 6 rows, register sliding window, float4 stores.
// blockIdx.x = nc*2 + half;  half-tile covers output rows [half*48, half*48+48)
// tile row i = global row (half*48 - 1 + i), i in [0,50); OOB rows zeroed.
// ---------------------------------------------------------------------------
#define SW 98
#define TR 50            // tile rows (48 + 2 halo)
#define HALF 48
__global__ void __launch_bounds__(192, 8) conv_kernel(const float* __restrict__ x,
                                                      float* __restrict__ out) {
    __shared__ float tile[TR*SW];   // 19600 B
    __shared__ float fs[9];

    int bid  = blockIdx.x;
    int nc   = bid >> 1;
    int half = bid & 1;
    int h0   = half * HALF;
    int t    = threadIdx.x;          // 0..191

    if (t < 9) fs[t] = d_filt[nc*9 + t];

    // zero left/right halo columns: 50 rows x 2 = 100 cells
    if (t < 2*TR) {
        int row = t >> 1;
        tile[row*SW + ((t & 1) ? 97 : 0)] = 0.f;
    }

    // load interior: 50 rows x 24 float4-segments = 1200 units
    const float4* xp = (const float4*)(x + (size_t)nc * HW);
    for (int i = t; i < TR*24; i += 192) {
        int row = i / 24;            // tile row
        int seg = i - row * 24;      // float4 segment within row
        int gr  = h0 - 1 + row;      // global row
        float4 v = make_float4(0.f, 0.f, 0.f, 0.f);
        if (gr >= 0 && gr < HH) v = xp[gr * (WW/4) + seg];
        float* dst = &tile[row*SW + seg*4 + 1];
        dst[0] = v.x; dst[1] = v.y; dst[2] = v.z; dst[3] = v.w;
    }
    __syncthreads();

    float f0 = fs[0], f1 = fs[1], f2 = fs[2];
    float f3 = fs[3], f4 = fs[4], f5 = fs[5];
    float f6 = fs[6], f7 = fs[7], f8 = fs[8];

    int g   = t % 24;                // column group: output cols [4g, 4g+4)
    int y   = t / 24;                // row strip: local rows [6y, 6y+6)
    int lr0 = y * 6;

    // tile cols needed for outputs 4g..4g+3: tile[4g .. 4g+5] (tile col = global col + 1)
    const float* base = &tile[lr0*SW + 4*g];
    float4* op = (float4*)(out + (size_t)nc * HW + (h0 + lr0) * WW + 4*g);

    float a0,a1,a2,a3,a4,a5, b0,b1,b2,b3,b4,b5;
    a0=base[0]; a1=base[1]; a2=base[2]; a3=base[3]; a4=base[4]; a5=base[5]; base += SW;
    b0=base[0]; b1=base[1]; b2=base[2]; b3=base[3]; b4=base[4]; b5=base[5];

    #pragma unroll
    for (int i = 0; i < 6; i++) {
        base += SW;
        float c0=base[0], c1=base[1], c2=base[2], c3=base[3], c4=base[4], c5=base[5];
        float4 o4;
        o4.x = f0*a0+f1*a1+f2*a2 + f3*b0+f4*b1+f5*b2 + f6*c0+f7*c1+f8*c2;
        o4.y = f0*a1+f1*a2+f2*a3 + f3*b1+f4*b2+f5*b3 + f6*c1+f7*c2+f8*c3;
        o4.z = f0*a2+f1*a3+f2*a4 + f3*b2+f4*b3+f5*b4 + f6*c2+f7*c3+f8*c4;
        o4.w = f0*a3+f1*a4+f2*a5 + f3*b3+f4*b4+f5*b5 + f6*c3+f7*c4+f8*c5;
        op[i * (WW/4)] = o4;
        a0=b0; a1=b1; a2=b2; a3=b3; a4=b4; a5=b5;
        b0=c0; b1=c1; b2=c2; b3=c3; b4=c4; b5=c5;
    }
}

// ---------------------------------------------------------------------------
extern "C" void kernel_launch(void* const* d_in, const int* in_sizes, int n_in,
                              void* d_out, int out_size) {
    const float* x   = (const float*)d_in[0];
    const float* cfc = (const float*)d_in[1];
    const float* w1  = (const float*)d_in[2];
    const float* b1  = (const float*)d_in[3];
    const float* w2  = (const float*)d_in[4];
    const float* b2  = (const float*)d_in[5];
    float* out = (float*)d_out;

    stats_kernel<<<NN*CC, 256>>>(x, cfc);
    mlp_kernel<<<NN, 256>>>(w1, b1, w2, b2);
    conv_kernel<<<NN*CC*2, 192>>>(x, out);
}

// round 8
// speedup vs baseline: 1.0779x; 1.0779x over previous
#include <cuda_runtime.h>
#include <math.h>

// Problem constants
#define NN 16
#define CC 256
#define HH 96
#define WW 96
#define HW (HH*WW)          // 9216
#define RED 16
#define HID (CC/RED)        // 16
#define KK 3
#define DYN (CC*KK*KK)      // 2304
#define EPS 1e-5f

// Scratch (allocation-free rule: __device__ globals)
__device__ float d_g[NN*CC];      // sigmoid gate per (n,c)
__device__ float d_gap[NN*CC];    // g * mean  (== mean of srm)
__device__ float d_filt[NN*DYN];  // g-folded dynamic 3x3 filters

// ---------------------------------------------------------------------------
// Kernel 1: per-(n,c) mean/std -> gate g, gap = g*mean   (71.7% DRAM, keep)
// ---------------------------------------------------------------------------
__global__ void __launch_bounds__(256) stats_kernel(const float* __restrict__ x,
                                                    const float* __restrict__ cfc) {
    int nc = blockIdx.x;
    const float4* xp = (const float4*)(x + (size_t)nc * HW);

    float s = 0.f, s2 = 0.f;
    #pragma unroll
    for (int i = threadIdx.x; i < HW/4; i += 256) {
        float4 v = xp[i];
        s  += v.x + v.y + v.z + v.w;
        s2 += v.x*v.x + v.y*v.y + v.z*v.z + v.w*v.w;
    }
    #pragma unroll
    for (int o = 16; o; o >>= 1) {
        s  += __shfl_xor_sync(0xffffffffu, s,  o);
        s2 += __shfl_xor_sync(0xffffffffu, s2, o);
    }
    __shared__ float ss[8], ss2[8];
    int w = threadIdx.x >> 5;
    if ((threadIdx.x & 31) == 0) { ss[w] = s; ss2[w] = s2; }
    __syncthreads();
    if (threadIdx.x == 0) {
        s = 0.f; s2 = 0.f;
        #pragma unroll
        for (int i = 0; i < 8; i++) { s += ss[i]; s2 += ss2[i]; }
        float mean = s * (1.f / (float)HW);
        float var  = (s2 - s * mean) * (1.f / (float)(HW - 1));  // unbiased
        float stdv = sqrtf(var + EPS);
        int c = nc & (CC - 1);
        float z = mean * cfc[2*c] + stdv * cfc[2*c + 1];
        float g = 1.f / (1.f + __expf(-z));
        d_g[nc]   = g;
        d_gap[nc] = g * mean;
    }
}

// ---------------------------------------------------------------------------
// Kernel 2: tiny MLP -> dynamic filters (g folded in)
// ---------------------------------------------------------------------------
__global__ void __launch_bounds__(256) mlp_kernel(const float* __restrict__ w1,
                                                  const float* __restrict__ b1,
                                                  const float* __restrict__ w2,
                                                  const float* __restrict__ b2) {
    int n = blockIdx.x;
    __shared__ float gap_s[CC];
    __shared__ float hid_s[HID];

    gap_s[threadIdx.x] = d_gap[n*CC + threadIdx.x];
    __syncthreads();

    {
        int r = threadIdx.x >> 4;
        int p = threadIdx.x & 15;
        const float* wr = w1 + r * CC;
        float acc = 0.f;
        #pragma unroll
        for (int c = p; c < CC; c += 16) acc += gap_s[c] * wr[c];
        #pragma unroll
        for (int o = 8; o; o >>= 1) acc += __shfl_xor_sync(0xffffffffu, acc, o);
        if (p == 0) hid_s[r] = fmaxf(acc + b1[r], 0.f);
    }
    __syncthreads();

    for (int o = threadIdx.x; o < DYN; o += 256) {
        const float* wr = w2 + o * HID;
        float acc = b2[o];
        #pragma unroll
        for (int r = 0; r < HID; r++) acc += hid_s[r] * wr[r];
        int c = o / (KK*KK);
        d_filt[n*DYN + o] = acc * d_g[n*CC + c];
    }
}

// ---------------------------------------------------------------------------
// Kernel 3: depthwise 3x3 conv, 2 half-tiles per (n,c).
// Block order REVERSED vs stats so conv starts on the L2-hot tail of x.
// x loads use __ldcs (read-once), out stores use __stcs (evict-first)
// to keep out-writes from evicting still-needed x lines in L2.
// ---------------------------------------------------------------------------
#define SW 98
#define TR 50            // tile rows (48 + 2 halo)
#define HALF 48
__global__ void __launch_bounds__(192, 8) conv_kernel(const float* __restrict__ x,
                                                      float* __restrict__ out) {
    __shared__ float tile[TR*SW];   // 19600 B
    __shared__ float fs[9];

    int bid  = (int)gridDim.x - 1 - (int)blockIdx.x;   // REVERSED order
    int nc   = bid >> 1;
    int half = bid & 1;
    int h0   = half * HALF;
    int t    = threadIdx.x;          // 0..191

    if (t < 9) fs[t] = d_filt[nc*9 + t];

    // zero left/right halo columns: 50 rows x 2 = 100 cells
    if (t < 2*TR) {
        int row = t >> 1;
        tile[row*SW + ((t & 1) ? 97 : 0)] = 0.f;
    }

    // load interior: 50 rows x 24 float4-segments = 1200 units
    const float4* xp = (const float4*)(x + (size_t)nc * HW);
    for (int i = t; i < TR*24; i += 192) {
        int row = i / 24;            // tile row
        int seg = i - row * 24;      // float4 segment within row
        int gr  = h0 - 1 + row;      // global row
        float4 v = make_float4(0.f, 0.f, 0.f, 0.f);
        if (gr >= 0 && gr < HH) v = __ldcs(&xp[gr * (WW/4) + seg]);
        float* dst = &tile[row*SW + seg*4 + 1];
        dst[0] = v.x; dst[1] = v.y; dst[2] = v.z; dst[3] = v.w;
    }
    __syncthreads();

    float f0 = fs[0], f1 = fs[1], f2 = fs[2];
    float f3 = fs[3], f4 = fs[4], f5 = fs[5];
    float f6 = fs[6], f7 = fs[7], f8 = fs[8];

    int g   = t % 24;                // column group: output cols [4g, 4g+4)
    int y   = t / 24;                // row strip: local rows [6y, 6y+6)
    int lr0 = y * 6;

    const float* base = &tile[lr0*SW + 4*g];
    float4* op = (float4*)(out + (size_t)nc * HW + (h0 + lr0) * WW + 4*g);

    float a0,a1,a2,a3,a4,a5, b0,b1,b2,b3,b4,b5;
    a0=base[0]; a1=base[1]; a2=base[2]; a3=base[3]; a4=base[4]; a5=base[5]; base += SW;
    b0=base[0]; b1=base[1]; b2=base[2]; b3=base[3]; b4=base[4]; b5=base[5];

    #pragma unroll
    for (int i = 0; i < 6; i++) {
        base += SW;
        float c0=base[0], c1=base[1], c2=base[2], c3=base[3], c4=base[4], c5=base[5];
        float4 o4;
        o4.x = f0*a0+f1*a1+f2*a2 + f3*b0+f4*b1+f5*b2 + f6*c0+f7*c1+f8*c2;
        o4.y = f0*a1+f1*a2+f2*a3 + f3*b1+f4*b2+f5*b3 + f6*c1+f7*c2+f8*c3;
        o4.z = f0*a2+f1*a3+f2*a4 + f3*b2+f4*b3+f5*b4 + f6*c2+f7*c3+f8*c4;
        o4.w = f0*a3+f1*a4+f2*a5 + f3*b3+f4*b4+f5*b5 + f6*c3+f7*c4+f8*c5;
        __stcs(&op[i * (WW/4)], o4);
        a0=b0; a1=b1; a2=b2; a3=b3; a4=b4; a5=b5;
        b0=c0; b1=c1; b2=c2; b3=c3; b4=c4; b5=c5;
    }
}

// ---------------------------------------------------------------------------
extern "C" void kernel_launch(void* const* d_in, const int* in_sizes, int n_in,
                              void* d_out, int out_size) {
    const float* x   = (const float*)d_in[0];
    const float* cfc = (const float*)d_in[1];
    const float* w1  = (const float*)d_in[2];
    const float* b1  = (const float*)d_in[3];
    const float* w2  = (const float*)d_in[4];
    const float* b2  = (const float*)d_in[5];
    float* out = (float*)d_out;

    stats_kernel<<<NN*CC, 256>>>(x, cfc);
    mlp_kernel<<<NN, 256>>>(w1, b1, w2, b2);
    conv_kernel<<<NN*CC*2, 192>>>(x, out);
}